// round 5
// baseline (speedup 1.0000x reference)
#include <cuda_runtime.h>

#define NB 1024            // queries
#define NC 500000          // table rows
#define ND 64              // dim
#define NK 50              // final neighbours
#define NCHUNK 37          // C chunks (148 blocks = 1 wave on 148 SMs)
#define KC 16              // per-(query,chunk) candidates kept (register-resident)
#define TILE_C 128         // table rows staged in smem per tile
#define TPB 256            // threads per block = queries per block
#define CHUNK ((NC + NCHUNK - 1) / NCHUNK)   // 13514
#define NCAND (NCHUNK * KC)                  // 592 candidates per query at merge

typedef unsigned long long u64;

// scratch (device globals; no allocation allowed)
__device__ float g_cd[(size_t)NB * NCHUNK * KC];
__device__ int   g_ci[(size_t)NB * NCHUNK * KC];

__device__ __forceinline__ u64 ffma2(u64 a, u64 b, u64 c) {
#if __CUDA_ARCH__ >= 1000
    u64 d;
    asm("fma.rn.f32x2 %0, %1, %2, %3;" : "=l"(d) : "l"(a), "l"(b), "l"(c));
    return d;
#else
    float2 fa = *(float2*)&a, fb = *(float2*)&b, fc = *(float2*)&c;
    float2 fd; fd.x = fmaf(fa.x, fb.x, fc.x); fd.y = fmaf(fa.y, fb.y, fc.y);
    return *(u64*)&fd;
#endif
}
__device__ __forceinline__ u64 pack2(float lo, float hi) {
    u64 r; asm("mov.b64 %0, {%1, %2};" : "=l"(r) : "f"(lo), "f"(hi)); return r;
}
__device__ __forceinline__ float hsum2(u64 v) {
    float x, y; asm("mov.b64 {%0, %1}, %2;" : "=f"(x), "=f"(y) : "l"(v));
    return x + y;
}

// ---------------------------------------------------------------------------
// Kernel 1: fused distance + per-(query,chunk) top-KC.
// One thread = one query. smem table tile read via broadcast (all lanes same
// address). Distances via packed f32x2 FMA (exact fp32, 2 FMA/inst).
// ---------------------------------------------------------------------------
__global__ void __launch_bounds__(TPB)
topk_kernel(const float* __restrict__ keys, const float* __restrict__ tkeys) {
    __shared__ __align__(16) float s_t[TILE_C * ND];
    __shared__ float s_n[TILE_C];

    const int tid  = threadIdx.x;
    const int qidx = blockIdx.y * TPB + tid;
    const int c0   = blockIdx.x * CHUNK;
    const int c1   = min(c0 + CHUNK, NC);
    const float INF = __int_as_float(0x7f800000);

    // query into registers as 32 packed f32x2
    u64 q[ND / 2];
    {
        const float4* qp = (const float4*)(keys + (size_t)qidx * ND);
#pragma unroll
        for (int i = 0; i < ND / 4; i++) {
            float4 v = qp[i];
            q[2 * i]     = pack2(v.x, v.y);
            q[2 * i + 1] = pack2(v.z, v.w);
        }
    }

    // register-resident top-KC (unsorted buffer + tracked max)
    float tkd[KC]; int tki[KC];
#pragma unroll
    for (int k = 0; k < KC; k++) { tkd[k] = INF; tki[k] = -1; }
    float cmax = INF;
    int   mpos = 0;

    for (int tb = c0; tb < c1; tb += TILE_C) {
        __syncthreads();
        // cooperative coalesced tile load (zero-fill out-of-chunk rows)
#pragma unroll
        for (int ii = 0; ii < (TILE_C * ND / 4) / TPB; ii++) {   // 8 iters
            int i = ii * TPB + tid;
            int r = i >> 4, dd = i & 15;
            int cg = tb + r;
            float4 v = make_float4(0.f, 0.f, 0.f, 0.f);
            if (cg < c1) v = ((const float4*)(tkeys + (size_t)cg * ND))[dd];
            ((float4*)s_t)[i] = v;
        }
        __syncthreads();
        // row norms (2 threads per row)
        {
            int r = tid >> 1, h = tid & 1;
            const float* row = s_t + r * ND + h * 32;
            float nrm = 0.f;
#pragma unroll
            for (int j = 0; j < 32; j++) nrm = fmaf(row[j], row[j], nrm);
            nrm += __shfl_xor_sync(0xffffffffu, nrm, 1);
            if (h == 0) s_n[r] = (tb + r < c1) ? nrm : INF;
        }
        __syncthreads();

        // distances: 2 candidates per iteration, 4 independent FMA2 chains
#pragma unroll 1
        for (int cc = 0; cc < TILE_C; cc += 2) {
            const ulonglong2* t0 = (const ulonglong2*)(s_t + cc * ND);
            const ulonglong2* t1 = (const ulonglong2*)(s_t + (cc + 1) * ND);
            u64 a0 = 0, a1 = 0, b0 = 0, b1 = 0;
#pragma unroll
            for (int j = 0; j < ND / 4; j++) {   // 16 iters
                ulonglong2 x = t0[j];
                ulonglong2 y = t1[j];
                a0 = ffma2(q[2 * j],     x.x, a0);
                a1 = ffma2(q[2 * j + 1], x.y, a1);
                b0 = ffma2(q[2 * j],     y.x, b0);
                b1 = ffma2(q[2 * j + 1], y.y, b1);
            }
            float s0 = fmaf(-2.f, hsum2(a0) + hsum2(a1), s_n[cc]);
            float s1 = fmaf(-2.f, hsum2(b0) + hsum2(b1), s_n[cc + 1]);

            if (s0 < cmax) {
#pragma unroll
                for (int k = 0; k < KC; k++)
                    if (k == mpos) { tkd[k] = s0; tki[k] = tb + cc; }
                cmax = tkd[0]; mpos = 0;
#pragma unroll
                for (int k = 1; k < KC; k++)
                    if (tkd[k] > cmax) { cmax = tkd[k]; mpos = k; }
            }
            if (s1 < cmax) {
#pragma unroll
                for (int k = 0; k < KC; k++)
                    if (k == mpos) { tkd[k] = s1; tki[k] = tb + cc + 1; }
                cmax = tkd[0]; mpos = 0;
#pragma unroll
                for (int k = 1; k < KC; k++)
                    if (tkd[k] > cmax) { cmax = tkd[k]; mpos = k; }
            }
        }
    }

    float* od = g_cd + ((size_t)qidx * NCHUNK + blockIdx.x) * KC;
    int*   oi = g_ci + ((size_t)qidx * NCHUNK + blockIdx.x) * KC;
#pragma unroll
    for (int k = 0; k < KC; k++) { od[k] = tkd[k]; oi[k] = tki[k]; }
}

// ---------------------------------------------------------------------------
// Kernel 2: per-query merge of 592 candidates -> exact top-50 -> exact fp32
// squared distances -> inverse-distance weighted average.
// ---------------------------------------------------------------------------
__global__ void __launch_bounds__(256)
merge_kernel(const float* __restrict__ keys, const float* __restrict__ tkeys,
             const float* __restrict__ tvals, float* __restrict__ out) {
    __shared__ float md[NCAND];
    __shared__ int   mi[NCAND];
    __shared__ float qs[ND];
    __shared__ int   sel[NK];
    __shared__ float rv[8]; __shared__ int rp[8];
    __shared__ float ws[NK], wv[NK];

    const int q = blockIdx.x, tid = threadIdx.x;
    const float INF = __int_as_float(0x7f800000);

    for (int i = tid; i < NCAND; i += 256) {
        md[i] = g_cd[(size_t)q * NCAND + i];
        mi[i] = g_ci[(size_t)q * NCAND + i];
    }
    if (tid < ND) qs[tid] = keys[(size_t)q * ND + tid];
    __syncthreads();

    for (int k = 0; k < NK; k++) {
        float v = INF; int p = 0;
        for (int i = tid; i < NCAND; i += 256)
            if (md[i] < v) { v = md[i]; p = i; }
#pragma unroll
        for (int o = 16; o > 0; o >>= 1) {
            float ovv = __shfl_down_sync(0xffffffffu, v, o);
            int   opp = __shfl_down_sync(0xffffffffu, p, o);
            if (ovv < v) { v = ovv; p = opp; }
        }
        if ((tid & 31) == 0) { rv[tid >> 5] = v; rp[tid >> 5] = p; }
        __syncthreads();
        if (tid == 0) {
            float bv = rv[0]; int bp = rp[0];
#pragma unroll
            for (int w = 1; w < 8; w++)
                if (rv[w] < bv) { bv = rv[w]; bp = rp[w]; }
            sel[k] = mi[bp];
            md[bp] = INF;
        }
        __syncthreads();
    }

    if (tid < NK) {
        int nb = sel[tid];
        const float* row = tkeys + (size_t)nb * ND;
        float sq = 0.f;
#pragma unroll
        for (int d = 0; d < ND; d++) {
            float df = qs[d] - row[d];
            sq = fmaf(df, df, sq);
        }
        float w = 1.0f / (sq + 1e-3f);
        ws[tid] = w;
        wv[tid] = w * tvals[nb];
    }
    __syncthreads();
    if (tid == 0) {
        float sw = 0.f, sv = 0.f;
#pragma unroll
        for (int k = 0; k < NK; k++) { sw += ws[k]; sv += wv[k]; }
        out[q] = sv / sw;
    }
}

extern "C" void kernel_launch(void* const* d_in, const int* in_sizes, int n_in,
                              void* d_out, int out_size) {
    const float* keys  = (const float*)d_in[0];   // [1024, 64]
    const float* tkeys = (const float*)d_in[1];   // [500000, 64]
    const float* tvals = (const float*)d_in[2];   // [500000]
    float* out = (float*)d_out;                   // [1024]

    dim3 g1(NCHUNK, NB / TPB);
    topk_kernel<<<g1, TPB>>>(keys, tkeys);
    merge_kernel<<<NB, 256>>>(keys, tkeys, tvals, out);
}

// round 9
// speedup vs baseline: 1.3031x; 1.3031x over previous
#include <cuda_runtime.h>
#include <cuda_fp16.h>
#include <cstdint>

#define NB 1024
#define NC 500000
#define ND 64
#define NK 50
#define NCH 18                       // chunks (grid.x)
#define CHUNK_SRC 27778              // source rows per chunk
#define TPC 218                      // 128-row tiles per chunk (padded)
#define PADC (TPC * 128)             // 27904
#define NT_TOTAL (NCH * TPC)         // 3924 tiles
#define KC2 10                       // per-thread-per-row candidates
#define NCAND (NCH * 40)             // 720 merge candidates per query

// smem layout (bytes)
#define SQ_OFF 0
#define ST_OFF 16384
#define SN_OFF 65536                 // 3 x 512
#define SMEM_TOTAL 67072

typedef unsigned int u32;
typedef unsigned long long u64;

// ------------------------- device-global scratch ---------------------------
__device__ __align__(16) unsigned char g_th[(size_t)NT_TOTAL * 16384]; // fp16 swizzled tiles
__device__ __align__(16) float g_nrm[(size_t)NT_TOTAL * 128];          // norms (INF pad)
__device__ int g_ci[(size_t)NB * NCAND];                               // candidate rows

// ------------------------------ helpers ------------------------------------
__device__ __forceinline__ u32 smem_u32(const void* p) {
    u32 a;
    asm("{ .reg .u64 t; cvta.to.shared.u64 t, %1; cvt.u32.u64 %0, t; }" : "=r"(a) : "l"(p));
    return a;
}
__device__ __forceinline__ u32 off16(u32 row, u32 kk) {
    return row * 128u + ((kk ^ (row & 7u)) << 4);
}
// order-preserving float -> u32 (handles negative scores correctly)
__device__ __forceinline__ u32 mono(float s) {
    u32 fb = __float_as_uint(s);
    return fb ^ (0x80000000u | (u32)((int)fb >> 31));
}
__device__ __forceinline__ void cpa16(u32 s, const void* g) {
    asm volatile("cp.async.cg.shared.global [%0], [%1], 16;" :: "r"(s), "l"(g));
}
__device__ __forceinline__ void cpa_commit() { asm volatile("cp.async.commit_group;" ::: "memory"); }
__device__ __forceinline__ void cpa_wait2()  { asm volatile("cp.async.wait_group 2;" ::: "memory"); }

__device__ __forceinline__ void ldsm_x4(u32& r0, u32& r1, u32& r2, u32& r3, u32 addr) {
    asm volatile("ldmatrix.sync.aligned.m8n8.x4.shared.b16 {%0,%1,%2,%3}, [%4];"
                 : "=r"(r0), "=r"(r1), "=r"(r2), "=r"(r3) : "r"(addr));
}
__device__ __forceinline__ void mma16816(float* c, const u32* a, u32 b0, u32 b1) {
    asm volatile(
        "mma.sync.aligned.m16n8k16.row.col.f32.f16.f16.f32 "
        "{%0,%1,%2,%3}, {%4,%5,%6,%7}, {%8,%9}, {%0,%1,%2,%3};"
        : "+f"(c[0]), "+f"(c[1]), "+f"(c[2]), "+f"(c[3])
        : "r"(a[0]), "r"(a[1]), "r"(a[2]), "r"(a[3]), "r"(b0), "r"(b1));
}

// ---------------------------------------------------------------------------
// prep: fp32 table -> fp16, pre-swizzled 16KB tiles + exact fp32 norms
// ---------------------------------------------------------------------------
__global__ void __launch_bounds__(128)
prep_kernel(const float* __restrict__ tkeys) {
    const int tile = blockIdx.x;
    const int r = threadIdx.x;
    const size_t p = (size_t)tile * 128 + r;
    const int c = (int)(p / PADC);
    const int l = (int)(p % PADC);
    const int srcsz = min(CHUNK_SRC, NC - c * CHUNK_SRC);
    const bool valid = l < srcsz;
    const size_t src = (size_t)c * CHUNK_SRC + l;

    float v[ND];
    if (valid) {
        const float4* sp = (const float4*)(tkeys + src * ND);
#pragma unroll
        for (int i = 0; i < ND / 4; i++) {
            float4 x = __ldg(sp + i);
            v[4 * i] = x.x; v[4 * i + 1] = x.y; v[4 * i + 2] = x.z; v[4 * i + 3] = x.w;
        }
    } else {
#pragma unroll
        for (int i = 0; i < ND; i++) v[i] = 0.f;
    }
    float nrm = 0.f;
#pragma unroll
    for (int i = 0; i < ND; i++) nrm = fmaf(v[i], v[i], nrm);

    unsigned char* th = g_th + (size_t)tile * 16384;
#pragma unroll
    for (int kk = 0; kk < 8; kk++) {
        u32 w[4];
#pragma unroll
        for (int e = 0; e < 4; e++) {
            __half h0 = __float2half(v[kk * 8 + 2 * e]);
            __half h1 = __float2half(v[kk * 8 + 2 * e + 1]);
            w[e] = (u32)__half_as_ushort(h0) | ((u32)__half_as_ushort(h1) << 16);
        }
        *(uint4*)(th + off16(r, kk)) = make_uint4(w[0], w[1], w[2], w[3]);
    }
    g_nrm[p] = valid ? nrm : __int_as_float(0x7f800000);
}

// ---------------------------------------------------------------------------
// topk: fp16 mma.sync GEMM + fused per-thread top-KC2 (monotonic score|idx)
// ---------------------------------------------------------------------------
__global__ void __launch_bounds__(256, 1)
topk_kernel(const float* __restrict__ keys) {
    extern __shared__ __align__(1024) unsigned char smem[];
    const u32 sb = smem_u32(smem);
    const int tid = threadIdx.x;
    const int w = tid >> 5, lane = tid & 31;
    const int lsub = lane >> 3, lrow = lane & 7;
    const int chunk = blockIdx.x;
    const int qbase = blockIdx.y * 128;

    // ---- stage queries into smem as swizzled fp16 (2 threads per row) ----
    {
        const int row = tid >> 1, half = tid & 1;
        const float4* qp = (const float4*)(keys + (size_t)(qbase + row) * ND + half * 32);
        float v[32];
#pragma unroll
        for (int i = 0; i < 8; i++) {
            float4 x = qp[i];
            v[4 * i] = x.x; v[4 * i + 1] = x.y; v[4 * i + 2] = x.z; v[4 * i + 3] = x.w;
        }
#pragma unroll
        for (int j = 0; j < 4; j++) {
            u32 wd[4];
#pragma unroll
            for (int e = 0; e < 4; e++) {
                __half h0 = __float2half(v[j * 8 + 2 * e]);
                __half h1 = __float2half(v[j * 8 + 2 * e + 1]);
                wd[e] = (u32)__half_as_ushort(h0) | ((u32)__half_as_ushort(h1) << 16);
            }
            *(uint4*)(smem + SQ_OFF + off16(row, half * 4 + j)) =
                make_uint4(wd[0], wd[1], wd[2], wd[3]);
        }
    }
    __syncthreads();

    // ---- A fragments (warp's 16 query rows), register-resident ----
    u32 afr[4][4];
    {
        const u32 arow = (u32)(w * 16 + lrow + ((lsub & 1) << 3));
        const u32 akk = (u32)(lsub >> 1);
#pragma unroll
        for (int kt = 0; kt < 4; kt++)
            ldsm_x4(afr[kt][0], afr[kt][1], afr[kt][2], afr[kt][3],
                    sb + SQ_OFF + off16(arow, kt * 2 + akk));
    }

    // ---- top-KC2 state: packed u32 (high 19 monotonic score bits | 13-bit idx)
    u32 P0[KC2], P1[KC2];
#pragma unroll
    for (int k = 0; k < KC2; k++) { P0[k] = 0xFFFFFFFFu; P1[k] = 0xFFFFFFFFu; }
    u32 cm0 = 0xFFFFFFFFu, cm1 = 0xFFFFFFFFu;
    int mp0 = 0, mp1 = 0;

#define INS(P, CM, MP, pk)                                        \
    if ((pk) < CM) {                                              \
        _Pragma("unroll")                                         \
        for (int k = 0; k < KC2; k++) if (k == MP) P[k] = (pk);   \
        CM = P[0]; MP = 0;                                        \
        _Pragma("unroll")                                         \
        for (int k = 1; k < KC2; k++)                             \
            if (P[k] > CM) { CM = P[k]; MP = k; }                 \
    }

    // ---- prefetch helper ----
    const int gt0 = chunk * TPC;
    auto prefetch = [&](int t, int st) {
        const unsigned char* src = g_th + (size_t)(gt0 + t) * 16384;
        u32 dst = sb + ST_OFF + st * 16384;
#pragma unroll
        for (int i = 0; i < 4; i++) {
            int o = tid * 16 + i * 4096;
            cpa16(dst + o, src + o);
        }
        if (tid < 32)
            cpa16(sb + SN_OFF + st * 512 + tid * 16,
                  (const unsigned char*)(g_nrm + (size_t)(gt0 + t) * 128) + tid * 16);
        cpa_commit();
    };

    prefetch(0, 0); prefetch(1, 1); prefetch(2, 2);

    const u32 brow = (u32)(lrow + ((lsub >> 1) << 3));
    const u32 bkk = (u32)(lsub & 1);
    const int cpair = lane & 3;

    for (int t = 0; t < TPC; t++) {
        const int st = t % 3;
        cpa_wait2();
        __syncthreads();

        float acc[64];
#pragma unroll
        for (int i = 0; i < 64; i++) acc[i] = 0.f;

        const u32 tb = sb + ST_OFF + st * 16384;
#pragma unroll
        for (int kt = 0; kt < 4; kt++) {
#pragma unroll
            for (int ng = 0; ng < 8; ng++) {
                u32 r0, r1, r2, r3;
                ldsm_x4(r0, r1, r2, r3, tb + off16(ng * 16 + brow, kt * 2 + bkk));
                mma16816(acc + ng * 8,     afr[kt], r0, r1);
                mma16816(acc + ng * 8 + 4, afr[kt], r2, r3);
            }
        }

        // epilogue: s = ||t||^2 - 2 dot ; insert monotonic-packed key
        const float2* np = (const float2*)(smem + SN_OFF + st * 512);
        const u32 tbase = (u32)t * 32u;
#pragma unroll
        for (int nt = 0; nt < 16; nt++) {
            float2 nv = np[nt * 4 + cpair];
            float s0 = fmaf(-2.f, acc[nt * 4 + 0], nv.x);
            float s1 = fmaf(-2.f, acc[nt * 4 + 1], nv.y);
            float s2 = fmaf(-2.f, acc[nt * 4 + 2], nv.x);
            float s3 = fmaf(-2.f, acc[nt * 4 + 3], nv.y);
            u32 i0 = tbase + nt * 2, i1 = i0 + 1;
            u32 p0 = (mono(s0) & 0xFFFFE000u) | i0;
            u32 p1 = (mono(s1) & 0xFFFFE000u) | i1;
            u32 p2 = (mono(s2) & 0xFFFFE000u) | i0;
            u32 p3 = (mono(s3) & 0xFFFFE000u) | i1;
            INS(P0, cm0, mp0, p0);
            INS(P0, cm0, mp0, p1);
            INS(P1, cm1, mp1, p2);
            INS(P1, cm1, mp1, p3);
        }

        __syncthreads();
        if (t + 3 < TPC) prefetch(t + 3, st);
        else cpa_commit();
    }
#undef INS

    // ---- decode + write candidates ----
    {
        const int q0 = qbase + w * 16 + (lane >> 2);
        const int col2 = (lane & 3) * 2;
        const int base0 = chunk * 40 + (lane & 3) * 10;
#pragma unroll
        for (int k = 0; k < KC2; k++) {
            u32 idx = P0[k] & 0x1FFFu;
            int loc = (int)(idx & 31u);
            int n = (loc >> 1) * 8 + col2 + (loc & 1);
            int row = chunk * CHUNK_SRC + (int)(idx >> 5) * 128 + n;
            g_ci[(size_t)q0 * NCAND + base0 + k] = min(row, NC - 1);
        }
#pragma unroll
        for (int k = 0; k < KC2; k++) {
            u32 idx = P1[k] & 0x1FFFu;
            int loc = (int)(idx & 31u);
            int n = (loc >> 1) * 8 + col2 + (loc & 1);
            int row = chunk * CHUNK_SRC + (int)(idx >> 5) * 128 + n;
            g_ci[(size_t)(q0 + 8) * NCAND + base0 + k] = min(row, NC - 1);
        }
    }
}

// ---------------------------------------------------------------------------
// merge: exact fp32 rerank of 720 candidates -> top-50 -> weighted average
// ---------------------------------------------------------------------------
__global__ void __launch_bounds__(256)
merge_kernel(const float* __restrict__ keys, const float* __restrict__ tkeys,
             const float* __restrict__ tvals, float* __restrict__ out) {
    __shared__ __align__(16) float qs[ND];
    __shared__ int   si[NCAND];
    __shared__ float sd[NCAND];
    __shared__ int   sel[NK];
    __shared__ float selv[NK];
    __shared__ float rv[8]; __shared__ int rp[8];
    __shared__ float ws[NK], wv[NK];

    const int q = blockIdx.x, tid = threadIdx.x;
    const int w = tid >> 5, lane = tid & 31;
    const float INF = __int_as_float(0x7f800000);

    for (int i = tid; i < NCAND; i += 256) si[i] = g_ci[(size_t)q * NCAND + i];
    if (tid < ND) qs[tid] = keys[(size_t)q * ND + tid];
    __syncthreads();

    // exact squared distances: warp per candidate, 2-way ILP
    {
        const float2 qv = ((const float2*)qs)[lane];
        for (int cb = w; cb < NCAND; cb += 16) {
            const int ra = si[cb], rb = si[cb + 8];
            const float2 ta = ((const float2*)(tkeys + (size_t)ra * ND))[lane];
            const float2 tb = ((const float2*)(tkeys + (size_t)rb * ND))[lane];
            float a0 = qv.x - ta.x, a1 = qv.y - ta.y;
            float b0 = qv.x - tb.x, b1 = qv.y - tb.y;
            float sa = fmaf(a0, a0, a1 * a1);
            float sc = fmaf(b0, b0, b1 * b1);
#pragma unroll
            for (int o = 16; o > 0; o >>= 1) {
                sa += __shfl_xor_sync(0xffffffffu, sa, o);
                sc += __shfl_xor_sync(0xffffffffu, sc, o);
            }
            if (lane == 0) { sd[cb] = sa; sd[cb + 8] = sc; }
        }
    }
    __syncthreads();

    // exact top-50 by iterative argmin
    for (int k = 0; k < NK; k++) {
        float v = INF; int p = 0;
        for (int i = tid; i < NCAND; i += 256)
            if (sd[i] < v) { v = sd[i]; p = i; }
#pragma unroll
        for (int o = 16; o > 0; o >>= 1) {
            float ov = __shfl_down_sync(0xffffffffu, v, o);
            int   op = __shfl_down_sync(0xffffffffu, p, o);
            if (ov < v) { v = ov; p = op; }
        }
        if (lane == 0) { rv[w] = v; rp[w] = p; }
        __syncthreads();
        if (tid == 0) {
            float bv = rv[0]; int bp = rp[0];
#pragma unroll
            for (int x = 1; x < 8; x++)
                if (rv[x] < bv) { bv = rv[x]; bp = rp[x]; }
            sel[k] = bp; selv[k] = bv;
            sd[bp] = INF;
        }
        __syncthreads();
    }

    if (tid < NK) {
        float wgt = 1.0f / (selv[tid] + 1e-3f);
        ws[tid] = wgt;
        wv[tid] = wgt * tvals[si[sel[tid]]];
    }
    __syncthreads();
    if (tid == 0) {
        float sw = 0.f, sv = 0.f;
#pragma unroll
        for (int k = 0; k < NK; k++) { sw += ws[k]; sv += wv[k]; }
        out[q] = sv / sw;
    }
}

// ---------------------------------------------------------------------------
extern "C" void kernel_launch(void* const* d_in, const int* in_sizes, int n_in,
                              void* d_out, int out_size) {
    const float* keys  = (const float*)d_in[0];   // [1024, 64]
    const float* tkeys = (const float*)d_in[1];   // [500000, 64]
    const float* tvals = (const float*)d_in[2];   // [500000]
    float* out = (float*)d_out;                   // [1024]

    cudaFuncSetAttribute(topk_kernel, cudaFuncAttributeMaxDynamicSharedMemorySize,
                         SMEM_TOTAL);

    prep_kernel<<<NT_TOTAL, 128>>>(tkeys);
    topk_kernel<<<dim3(NCH, 8), 256, SMEM_TOTAL>>>(keys);
    merge_kernel<<<NB, 256>>>(keys, tkeys, tvals, out);
}

// round 10
// speedup vs baseline: 1.6163x; 1.2403x over previous
#include <cuda_runtime.h>
#include <cstdint>

#define NB 1024
#define NC 500000
#define ND 64
#define NK 50
#define NR 148                 // ranges = CTAs = one per SM
#define RC 3456                // columns per range = 27 tiles x 128
#define TPT 27                 // tiles per range
#define NPAD (NR * RC)         // 511488 padded rows
#define KCR 10                 // keys kept per (query, range)
#define NCAND (NR * KCR)       // 1480 candidates per query
#define NSEL 112               // exact-reranked superset
#define QS 25.0f               // int8 quant scale
#define KEYBASE 268435456      // 65536 << 12

typedef unsigned int u32;

// ------------------------- device-global scratch ---------------------------
__device__ __align__(16) unsigned char g_t8[(size_t)NPAD * 64];  // packed int8 table
__device__ int g_nint[NPAD];                                     // int norms (pad=200000)
__device__ __align__(16) unsigned char g_q8[NB * 64];            // packed int8 queries
__device__ u32 g_key[(size_t)NB * NCAND];                        // packed (score|col) keys

// ------------------------------ helpers ------------------------------------
__device__ __forceinline__ u32 smem_u32(const void* p) {
    u32 a;
    asm("{ .reg .u64 t; cvta.to.shared.u64 t, %1; cvt.u32.u64 %0, t; }" : "=r"(a) : "l"(p));
    return a;
}
__device__ __forceinline__ void cpa16(u32 s, const void* g) {
    asm volatile("cp.async.cg.shared.global [%0], [%1], 16;" :: "r"(s), "l"(g));
}
__device__ __forceinline__ void cpa_commit() { asm volatile("cp.async.commit_group;" ::: "memory"); }
__device__ __forceinline__ void cpa_wait2()  { asm volatile("cp.async.wait_group 2;" ::: "memory"); }

__device__ __forceinline__ void quant_row(const float* v, u32* w, int& nint) {
    nint = 0;
#pragma unroll
    for (int j = 0; j < 16; j++) {
        u32 pk = 0;
#pragma unroll
        for (int e = 0; e < 4; e++) {
            int r = __float2int_rn(v[j * 4 + e] * QS);
            r = max(-127, min(127, r));
            nint += r * r;
            pk |= ((u32)(r & 255)) << (8 * e);
        }
        w[j] = pk;
    }
}

// ---------------------------------------------------------------------------
// prep_t: fp32 table -> packed int8 rows + int norms (padded)
// ---------------------------------------------------------------------------
__global__ void __launch_bounds__(256)
prep_t(const float* __restrict__ tkeys) {
    const int p = blockIdx.x * 256 + threadIdx.x;   // grid covers NPAD exactly
    u32 w[16];
    int nint;
    if (p < NC) {
        float v[ND];
        const float4* sp = (const float4*)(tkeys + (size_t)p * ND);
#pragma unroll
        for (int i = 0; i < 16; i++) {
            float4 x = __ldg(sp + i);
            v[4 * i] = x.x; v[4 * i + 1] = x.y; v[4 * i + 2] = x.z; v[4 * i + 3] = x.w;
        }
        quant_row(v, w, nint);
    } else {
#pragma unroll
        for (int i = 0; i < 16; i++) w[i] = 0;
        nint = 200000;                               // pad: key always worst
    }
    uint4* dst = (uint4*)(g_t8 + (size_t)p * 64);
    dst[0] = make_uint4(w[0], w[1], w[2], w[3]);
    dst[1] = make_uint4(w[4], w[5], w[6], w[7]);
    dst[2] = make_uint4(w[8], w[9], w[10], w[11]);
    dst[3] = make_uint4(w[12], w[13], w[14], w[15]);
    g_nint[p] = nint;
}

// prep_q: quantize queries
__global__ void __launch_bounds__(256)
prep_q(const float* __restrict__ keys) {
    const int p = blockIdx.x * 256 + threadIdx.x;
    if (p >= NB) return;
    float v[ND];
    const float4* sp = (const float4*)(keys + (size_t)p * ND);
#pragma unroll
    for (int i = 0; i < 16; i++) {
        float4 x = __ldg(sp + i);
        v[4 * i] = x.x; v[4 * i + 1] = x.y; v[4 * i + 2] = x.z; v[4 * i + 3] = x.w;
    }
    u32 w[16]; int nint;
    quant_row(v, w, nint);
    uint4* dst = (uint4*)(g_q8 + (size_t)p * 64);
    dst[0] = make_uint4(w[0], w[1], w[2], w[3]);
    dst[1] = make_uint4(w[4], w[5], w[6], w[7]);
    dst[2] = make_uint4(w[8], w[9], w[10], w[11]);
    dst[3] = make_uint4(w[12], w[13], w[14], w[15]);
}

// ---------------------------------------------------------------------------
// topk: dp4a distance sweep + fused per-(query,range) top-KCR
// one CTA per range (148 = one wave); each thread owns 4 queries
// ---------------------------------------------------------------------------
__global__ void __launch_bounds__(256, 1)
topk_kernel() {
    __shared__ __align__(16) u32 s_t[3][2048];      // 3 x 8KB tile (128 cols x 64B)
    __shared__ __align__(16) int s_n[3][128];       // 3 x norm tile

    const int tid = threadIdx.x;
    const int range = blockIdx.x;
    const int q0 = tid * 4;
    const u32 sbt = smem_u32(&s_t[0][0]);
    const u32 sbn = smem_u32(&s_n[0][0]);

    // queries -> registers (packed int8 words)
    u32 q[4][16];
#pragma unroll
    for (int qi = 0; qi < 4; qi++) {
        const uint4* qp = (const uint4*)(g_q8 + (size_t)(q0 + qi) * 64);
#pragma unroll
        for (int i = 0; i < 4; i++) {
            uint4 x = qp[i];
            q[qi][4 * i] = x.x; q[qi][4 * i + 1] = x.y;
            q[qi][4 * i + 2] = x.z; q[qi][4 * i + 3] = x.w;
        }
    }

    // top-KCR per owned query (u32 keys, smaller = better)
    u32 P[4][KCR];
    u32 cm[4]; int mp[4];
#pragma unroll
    for (int qi = 0; qi < 4; qi++) {
#pragma unroll
        for (int k = 0; k < KCR; k++) P[qi][k] = 0xFFFFFFFFu;
        cm[qi] = 0xFFFFFFFFu; mp[qi] = 0;
    }

#define INS(QI, PK)                                                   \
    {                                                                 \
        _Pragma("unroll")                                             \
        for (int k = 0; k < KCR; k++)                                 \
            if (k == mp[QI]) P[QI][k] = (PK);                         \
        cm[QI] = P[QI][0]; mp[QI] = 0;                                \
        _Pragma("unroll")                                             \
        for (int k = 1; k < KCR; k++)                                 \
            if (P[QI][k] > cm[QI]) { cm[QI] = P[QI][k]; mp[QI] = k; } \
    }

    const size_t rbase = (size_t)range * RC;
    auto prefetch = [&](int t, int st) {
        const unsigned char* src = g_t8 + (rbase + (size_t)t * 128) * 64;
        u32 dst = sbt + st * 8192 + tid * 32;
        cpa16(dst, src + tid * 32);
        cpa16(dst + 16, src + tid * 32 + 16);
        if (tid < 32)
            cpa16(sbn + st * 512 + tid * 16,
                  (const unsigned char*)(g_nint + rbase + (size_t)t * 128) + tid * 16);
        cpa_commit();
    };

    prefetch(0, 0); prefetch(1, 1); prefetch(2, 2);

    for (int t = 0; t < TPT; t++) {
        const int st = t % 3;
        cpa_wait2();
        __syncthreads();

        const u32* tp = s_t[st];
        const int* np = s_n[st];
        const int base_c = KEYBASE + t * 128;

#pragma unroll 2
        for (int c = 0; c < 128; c += 2) {
            const uint4* ta = (const uint4*)(tp + c * 16);
            const uint4* tb = (const uint4*)(tp + (c + 1) * 16);
            uint4 a0 = ta[0], a1 = ta[1], a2 = ta[2], a3 = ta[3];
            uint4 b0 = tb[0], b1 = tb[1], b2 = tb[2], b3 = tb[3];
            const int na = np[c], nb = np[c + 1];
#pragma unroll
            for (int qi = 0; qi < 4; qi++) {
                int da = 0, db = 0;
                da = __dp4a((int)a0.x, (int)q[qi][0], da);
                db = __dp4a((int)b0.x, (int)q[qi][0], db);
                da = __dp4a((int)a0.y, (int)q[qi][1], da);
                db = __dp4a((int)b0.y, (int)q[qi][1], db);
                da = __dp4a((int)a0.z, (int)q[qi][2], da);
                db = __dp4a((int)b0.z, (int)q[qi][2], db);
                da = __dp4a((int)a0.w, (int)q[qi][3], da);
                db = __dp4a((int)b0.w, (int)q[qi][3], db);
                da = __dp4a((int)a1.x, (int)q[qi][4], da);
                db = __dp4a((int)b1.x, (int)q[qi][4], db);
                da = __dp4a((int)a1.y, (int)q[qi][5], da);
                db = __dp4a((int)b1.y, (int)q[qi][5], db);
                da = __dp4a((int)a1.z, (int)q[qi][6], da);
                db = __dp4a((int)b1.z, (int)q[qi][6], db);
                da = __dp4a((int)a1.w, (int)q[qi][7], da);
                db = __dp4a((int)b1.w, (int)q[qi][7], db);
                da = __dp4a((int)a2.x, (int)q[qi][8], da);
                db = __dp4a((int)b2.x, (int)q[qi][8], db);
                da = __dp4a((int)a2.y, (int)q[qi][9], da);
                db = __dp4a((int)b2.y, (int)q[qi][9], db);
                da = __dp4a((int)a2.z, (int)q[qi][10], da);
                db = __dp4a((int)b2.z, (int)q[qi][10], db);
                da = __dp4a((int)a2.w, (int)q[qi][11], da);
                db = __dp4a((int)b2.w, (int)q[qi][11], db);
                da = __dp4a((int)a3.x, (int)q[qi][12], da);
                db = __dp4a((int)b3.x, (int)q[qi][12], db);
                da = __dp4a((int)a3.y, (int)q[qi][13], da);
                db = __dp4a((int)b3.y, (int)q[qi][13], db);
                da = __dp4a((int)a3.z, (int)q[qi][14], da);
                db = __dp4a((int)b3.z, (int)q[qi][14], db);
                da = __dp4a((int)a3.w, (int)q[qi][15], da);
                db = __dp4a((int)b3.w, (int)q[qi][15], db);

                const int sa = na - 2 * da;          // exact int score * 625
                const int sb = nb - 2 * db;
                const u32 ka = (u32)(sa * 4096 + base_c + c);
                const u32 kb = (u32)(sb * 4096 + base_c + c + 1);
                const u32 kmin = umin(ka, kb);
                if (kmin < cm[qi]) {
                    if (ka < cm[qi]) INS(qi, ka);
                    if (kb < cm[qi]) INS(qi, kb);
                }
            }
        }

        __syncthreads();
        if (t + 3 < TPT) prefetch(t + 3, st);
        else cpa_commit();
    }
#undef INS

    // write keys
#pragma unroll
    for (int qi = 0; qi < 4; qi++) {
        u32* ok = g_key + (size_t)(q0 + qi) * NCAND + range * KCR;
#pragma unroll
        for (int k = 0; k < KCR; k++) ok[k] = P[qi][k];
    }
}

// ---------------------------------------------------------------------------
// merge: approx top-NSEL by key -> exact fp32 rerank -> exact top-50 -> output
// ---------------------------------------------------------------------------
__global__ void __launch_bounds__(256)
merge_kernel(const float* __restrict__ keys, const float* __restrict__ tkeys,
             const float* __restrict__ tvals, float* __restrict__ out) {
    __shared__ u32 skey[NCAND];
    __shared__ int selrow[NSEL];
    __shared__ float sd[NSEL];
    __shared__ __align__(16) float qs[ND];
    __shared__ u32 rv[8]; __shared__ int rp[8];
    __shared__ float frv[8]; __shared__ int frp[8];
    __shared__ float selv[NK];
    __shared__ int sel2[NK];
    __shared__ float ws[NK], wv[NK];

    const int q = blockIdx.x, tid = threadIdx.x;
    const int w = tid >> 5, lane = tid & 31;
    const float INF = __int_as_float(0x7f800000);

    for (int i = tid; i < NCAND; i += 256) skey[i] = g_key[(size_t)q * NCAND + i];
    if (tid < ND) qs[tid] = keys[(size_t)q * ND + tid];
    __syncthreads();

    // stage 1: approx top-NSEL via iterative argmin on u32 keys
    for (int k = 0; k < NSEL; k++) {
        u32 v = 0xFFFFFFFFu; int p = 0;
        for (int i = tid; i < NCAND; i += 256)
            if (skey[i] < v) { v = skey[i]; p = i; }
#pragma unroll
        for (int o = 16; o > 0; o >>= 1) {
            u32 ov = __shfl_down_sync(0xffffffffu, v, o);
            int op = __shfl_down_sync(0xffffffffu, p, o);
            if (ov < v) { v = ov; p = op; }
        }
        if (lane == 0) { rv[w] = v; rp[w] = p; }
        __syncthreads();
        if (tid == 0) {
            u32 bv = rv[0]; int bp = rp[0];
#pragma unroll
            for (int x = 1; x < 8; x++)
                if (rv[x] < bv) { bv = rv[x]; bp = rp[x]; }
            int row = (bp / KCR) * RC + (int)(skey[bp] & 4095u);
            selrow[k] = min(row, NC - 1);
            skey[bp] = 0xFFFFFFFFu;
        }
        __syncthreads();
    }

    // exact fp32 rerank: warp per candidate
    {
        const float2 qv = ((const float2*)qs)[lane];
        for (int cb = w; cb < NSEL; cb += 8) {
            const int row = selrow[cb];
            const float2 tv = ((const float2*)(tkeys + (size_t)row * ND))[lane];
            float d0 = qv.x - tv.x, d1 = qv.y - tv.y;
            float ss = fmaf(d0, d0, d1 * d1);
#pragma unroll
            for (int o = 16; o > 0; o >>= 1) ss += __shfl_xor_sync(0xffffffffu, ss, o);
            if (lane == 0) sd[cb] = ss;
        }
    }
    __syncthreads();

    // stage 2: exact top-50 of NSEL
    for (int k = 0; k < NK; k++) {
        float v = INF; int p = 0;
        if (tid < NSEL && sd[tid] < v) { v = sd[tid]; p = tid; }
#pragma unroll
        for (int o = 16; o > 0; o >>= 1) {
            float ov = __shfl_down_sync(0xffffffffu, v, o);
            int   op = __shfl_down_sync(0xffffffffu, p, o);
            if (ov < v) { v = ov; p = op; }
        }
        if (lane == 0) { frv[w] = v; frp[w] = p; }
        __syncthreads();
        if (tid == 0) {
            float bv = frv[0]; int bp = frp[0];
#pragma unroll
            for (int x = 1; x < 8; x++)
                if (frv[x] < bv) { bv = frv[x]; bp = frp[x]; }
            selv[k] = bv; sel2[k] = bp;
            sd[bp] = INF;
        }
        __syncthreads();
    }

    if (tid < NK) {
        float wgt = 1.0f / (selv[tid] + 1e-3f);
        ws[tid] = wgt;
        wv[tid] = wgt * tvals[selrow[sel2[tid]]];
    }
    __syncthreads();
    if (tid == 0) {
        float sw = 0.f, sv = 0.f;
#pragma unroll
        for (int k = 0; k < NK; k++) { sw += ws[k]; sv += wv[k]; }
        out[q] = sv / sw;
    }
}

// ---------------------------------------------------------------------------
extern "C" void kernel_launch(void* const* d_in, const int* in_sizes, int n_in,
                              void* d_out, int out_size) {
    const float* keys  = (const float*)d_in[0];   // [1024, 64]
    const float* tkeys = (const float*)d_in[1];   // [500000, 64]
    const float* tvals = (const float*)d_in[2];   // [500000]
    float* out = (float*)d_out;                   // [1024]

    prep_t<<<NPAD / 256, 256>>>(tkeys);           // 1998 blocks, exact cover
    prep_q<<<4, 256>>>(keys);
    topk_kernel<<<NR, 256>>>();
    merge_kernel<<<NB, 256>>>(keys, tkeys, tvals, out);
}

// round 11
// speedup vs baseline: 3.0803x; 1.9058x over previous
#include <cuda_runtime.h>
#include <cstdint>

#define NB 1024
#define NC 500000
#define ND 64
#define NK 50
#define NR 148                 // sweep CTAs = one per SM
#define RC 3456                // columns per range = 27 tiles x 128
#define TPT 27
#define NPAD (NR * RC)         // 511488 padded rows
#define CAP 6144               // per-query candidate capacity
#define QS 25.0f
#define NSMP 4096              // tau sample size
#define SSTRIDE 122            // 4095*122 = 499590 < NC
#define NTAU 12                // tau = 12th smallest sample score

typedef unsigned int u32;

// ------------------------- device-global scratch ---------------------------
__device__ __align__(16) unsigned char g_t8[(size_t)NPAD * 64];  // packed int8 table
__device__ int g_nint[NPAD];                                     // int norms (pad huge)
__device__ __align__(16) unsigned char g_q8[NB * 64];            // packed int8 queries
__device__ int g_tau[NB];                                        // per-query threshold
__device__ u32 g_cnt[NB];                                        // per-query counts
__device__ int g_cand[(size_t)NB * CAP];                         // candidate rows

// ------------------------------ helpers ------------------------------------
__device__ __forceinline__ u32 smem_u32(const void* p) {
    u32 a;
    asm("{ .reg .u64 t; cvta.to.shared.u64 t, %1; cvt.u32.u64 %0, t; }" : "=r"(a) : "l"(p));
    return a;
}
__device__ __forceinline__ void cpa16(u32 s, const void* g) {
    asm volatile("cp.async.cg.shared.global [%0], [%1], 16;" :: "r"(s), "l"(g));
}
__device__ __forceinline__ void cpa_commit() { asm volatile("cp.async.commit_group;" ::: "memory"); }
__device__ __forceinline__ void cpa_wait2()  { asm volatile("cp.async.wait_group 2;" ::: "memory"); }

__device__ __forceinline__ void quant_row(const float* v, u32* w, int& nint) {
    nint = 0;
#pragma unroll
    for (int j = 0; j < 16; j++) {
        u32 pk = 0;
#pragma unroll
        for (int e = 0; e < 4; e++) {
            int r = __float2int_rn(v[j * 4 + e] * QS);
            r = max(-127, min(127, r));
            nint += r * r;
            pk |= ((u32)(r & 255)) << (8 * e);
        }
        w[j] = pk;
    }
}
__device__ __forceinline__ void load16(const unsigned char* src, u32* w) {
    const uint4* p = (const uint4*)src;
#pragma unroll
    for (int i = 0; i < 4; i++) {
        uint4 x = p[i];
        w[4 * i] = x.x; w[4 * i + 1] = x.y; w[4 * i + 2] = x.z; w[4 * i + 3] = x.w;
    }
}

// ---------------------------------------------------------------------------
// prep_t: fp32 table -> packed int8 rows + int norms (padded rows never qualify)
// ---------------------------------------------------------------------------
__global__ void __launch_bounds__(256)
prep_t(const float* __restrict__ tkeys) {
    const int p = blockIdx.x * 256 + threadIdx.x;   // grid covers NPAD exactly
    u32 w[16];
    int nint;
    if (p < NC) {
        float v[ND];
        const float4* sp = (const float4*)(tkeys + (size_t)p * ND);
#pragma unroll
        for (int i = 0; i < 16; i++) {
            float4 x = __ldg(sp + i);
            v[4 * i] = x.x; v[4 * i + 1] = x.y; v[4 * i + 2] = x.z; v[4 * i + 3] = x.w;
        }
        quant_row(v, w, nint);
    } else {
#pragma unroll
        for (int i = 0; i < 16; i++) w[i] = 0;
        nint = 1 << 29;                              // never below any tau
    }
    uint4* dst = (uint4*)(g_t8 + (size_t)p * 64);
    dst[0] = make_uint4(w[0], w[1], w[2], w[3]);
    dst[1] = make_uint4(w[4], w[5], w[6], w[7]);
    dst[2] = make_uint4(w[8], w[9], w[10], w[11]);
    dst[3] = make_uint4(w[12], w[13], w[14], w[15]);
    g_nint[p] = nint;
}

// prep_q: quantize queries
__global__ void __launch_bounds__(256)
prep_q(const float* __restrict__ keys) {
    const int p = blockIdx.x * 256 + threadIdx.x;
    if (p >= NB) return;
    float v[ND];
    const float4* sp = (const float4*)(keys + (size_t)p * ND);
#pragma unroll
    for (int i = 0; i < 16; i++) {
        float4 x = __ldg(sp + i);
        v[4 * i] = x.x; v[4 * i + 1] = x.y; v[4 * i + 2] = x.z; v[4 * i + 3] = x.w;
    }
    u32 w[16]; int nint;
    quant_row(v, w, nint);
    uint4* dst = (uint4*)(g_q8 + (size_t)p * 64);
    dst[0] = make_uint4(w[0], w[1], w[2], w[3]);
    dst[1] = make_uint4(w[4], w[5], w[6], w[7]);
    dst[2] = make_uint4(w[8], w[9], w[10], w[11]);
    dst[3] = make_uint4(w[12], w[13], w[14], w[15]);
}

// ---------------------------------------------------------------------------
// tau_kernel: per-query threshold from 4096-row sample; also resets counter
// ---------------------------------------------------------------------------
__global__ void __launch_bounds__(256)
tau_kernel() {
    __shared__ int s_s[NSMP];                 // 16KB sample scores
    __shared__ int rv[8], rp[8];
    __shared__ int s_tau;

    const int q = blockIdx.x, tid = threadIdx.x;
    const int w = tid >> 5, lane = tid & 31;

    u32 qw[16];
    load16(g_q8 + (size_t)q * 64, qw);

#pragma unroll
    for (int i = 0; i < NSMP / 256; i++) {
        const int j = tid + i * 256;
        const int r = j * SSTRIDE;
        u32 tw[16];
        load16(g_t8 + (size_t)r * 64, tw);
        int d = 0;
#pragma unroll
        for (int k = 0; k < 16; k++) d = __dp4a((int)tw[k], (int)qw[k], d);
        s_s[j] = g_nint[r] - 2 * d;
    }
    __syncthreads();

    for (int k = 0; k < NTAU; k++) {
        int v = 0x7FFFFFFF, p = 0;
        for (int i = tid; i < NSMP; i += 256)
            if (s_s[i] < v) { v = s_s[i]; p = i; }
#pragma unroll
        for (int o = 16; o > 0; o >>= 1) {
            int ov = __shfl_down_sync(0xffffffffu, v, o);
            int op = __shfl_down_sync(0xffffffffu, p, o);
            if (ov < v) { v = ov; p = op; }
        }
        if (lane == 0) { rv[w] = v; rp[w] = p; }
        __syncthreads();
        if (tid == 0) {
            int bv = rv[0], bp = rp[0];
#pragma unroll
            for (int x = 1; x < 8; x++)
                if (rv[x] < bv) { bv = rv[x]; bp = rp[x]; }
            s_s[bp] = 0x7FFFFFFF;
            if (k == NTAU - 1) s_tau = bv;
        }
        __syncthreads();
    }
    if (tid == 0) { g_tau[q] = s_tau; g_cnt[q] = 0u; }
}

// ---------------------------------------------------------------------------
// sweep: dp4a distance sweep, threshold test, append qualifiers (no top-K)
// 148 CTAs x 512 threads; thread owns queries 2t, 2t+1
// ---------------------------------------------------------------------------
__global__ void __launch_bounds__(512, 1)
sweep_kernel() {
    __shared__ __align__(16) u32 s_t[3][2048];   // 3 x 8KB tile
    __shared__ __align__(16) int s_n[3][128];

    const int tid = threadIdx.x;
    const int range = blockIdx.x;
    const int q0 = tid * 2, q1 = q0 + 1;
    const u32 sbt = smem_u32(&s_t[0][0]);
    const u32 sbn = smem_u32(&s_n[0][0]);

    u32 q0w[16], q1w[16];
    load16(g_q8 + (size_t)q0 * 64, q0w);
    load16(g_q8 + (size_t)q1 * 64, q1w);
    const int t0 = g_tau[q0] + 1;     // strict < t  <=>  s <= tau
    const int t1 = g_tau[q1] + 1;

    const size_t rbase = (size_t)range * RC;
    auto prefetch = [&](int t, int st) {
        const unsigned char* src = g_t8 + (rbase + (size_t)t * 128) * 64;
        cpa16(sbt + st * 8192 + tid * 16, src + tid * 16);
        if (tid < 32)
            cpa16(sbn + st * 512 + tid * 16,
                  (const unsigned char*)(g_nint + rbase + (size_t)t * 128) + tid * 16);
        cpa_commit();
    };

    prefetch(0, 0); prefetch(1, 1); prefetch(2, 2);

    for (int t = 0; t < TPT; t++) {
        const int st = t % 3;
        cpa_wait2();
        __syncthreads();

        const u32* tp = s_t[st];
        const int* np = s_n[st];
        const int pbase = range * RC + t * 128;

#pragma unroll 2
        for (int c = 0; c < 128; c += 2) {
            u32 aw[16], bw[16];
            load16((const unsigned char*)(tp + c * 16), aw);
            load16((const unsigned char*)(tp + (c + 1) * 16), bw);

            int da0 = 0, db0 = 0, da1 = 0, db1 = 0;
#pragma unroll
            for (int j = 0; j < 16; j++) {
                da0 = __dp4a((int)aw[j], (int)q0w[j], da0);
                db0 = __dp4a((int)bw[j], (int)q0w[j], db0);
                da1 = __dp4a((int)aw[j], (int)q1w[j], da1);
                db1 = __dp4a((int)bw[j], (int)q1w[j], db1);
            }
            const int na = np[c], nb = np[c + 1];
            const int sa0 = na - 2 * da0, sb0 = nb - 2 * db0;
            const int sa1 = na - 2 * da1, sb1 = nb - 2 * db1;
            const int m = min(min(sa0 - t0, sb0 - t0), min(sa1 - t1, sb1 - t1));
            if (m < 0) {
                const int p0 = pbase + c;
                if (sa0 < t0) {
                    u32 i = atomicAdd(&g_cnt[q0], 1u);
                    if (i < CAP) g_cand[(size_t)q0 * CAP + i] = p0;
                }
                if (sb0 < t0) {
                    u32 i = atomicAdd(&g_cnt[q0], 1u);
                    if (i < CAP) g_cand[(size_t)q0 * CAP + i] = p0 + 1;
                }
                if (sa1 < t1) {
                    u32 i = atomicAdd(&g_cnt[q1], 1u);
                    if (i < CAP) g_cand[(size_t)q1 * CAP + i] = p0;
                }
                if (sb1 < t1) {
                    u32 i = atomicAdd(&g_cnt[q1], 1u);
                    if (i < CAP) g_cand[(size_t)q1 * CAP + i] = p0 + 1;
                }
            }
        }

        __syncthreads();
        if (t + 3 < TPT) prefetch(t + 3, st);
        else cpa_commit();
    }
}

// ---------------------------------------------------------------------------
// merge: exact fp32 rerank of qualifiers -> exact top-50 -> weighted average
// ---------------------------------------------------------------------------
__global__ void __launch_bounds__(256)
merge_kernel(const float* __restrict__ keys, const float* __restrict__ tkeys,
             const float* __restrict__ tvals, float* __restrict__ out) {
    __shared__ float sd[CAP];                 // 24KB exact distances
    __shared__ __align__(16) float qs[ND];
    __shared__ float frv[8]; __shared__ int frp[8];
    __shared__ float selv[NK]; __shared__ int sel2[NK];
    __shared__ float ws[NK], wv[NK];

    const int q = blockIdx.x, tid = threadIdx.x;
    const int w = tid >> 5, lane = tid & 31;
    const float INF = __int_as_float(0x7f800000);
    const int n = min((int)g_cnt[q], CAP);
    const int* cand = g_cand + (size_t)q * CAP;

    if (tid < ND) qs[tid] = keys[(size_t)q * ND + tid];
    __syncthreads();

    // exact squared distances: warp per candidate (broadcast row index)
    {
        const float2 qv = ((const float2*)qs)[lane];
        for (int cb = w; cb < n; cb += 8) {
            const int row = cand[cb];
            const float2 tv = ((const float2*)(tkeys + (size_t)row * ND))[lane];
            float d0 = qv.x - tv.x, d1 = qv.y - tv.y;
            float ss = fmaf(d0, d0, d1 * d1);
#pragma unroll
            for (int o = 16; o > 0; o >>= 1) ss += __shfl_xor_sync(0xffffffffu, ss, o);
            if (lane == 0) sd[cb] = ss;
        }
    }
    __syncthreads();

    // exact top-50 by iterative argmin over n candidates
    for (int k = 0; k < NK; k++) {
        float v = INF; int p = 0;
        for (int i = tid; i < n; i += 256)
            if (sd[i] < v) { v = sd[i]; p = i; }
#pragma unroll
        for (int o = 16; o > 0; o >>= 1) {
            float ov = __shfl_down_sync(0xffffffffu, v, o);
            int   op = __shfl_down_sync(0xffffffffu, p, o);
            if (ov < v) { v = ov; p = op; }
        }
        if (lane == 0) { frv[w] = v; frp[w] = p; }
        __syncthreads();
        if (tid == 0) {
            float bv = frv[0]; int bp = frp[0];
#pragma unroll
            for (int x = 1; x < 8; x++)
                if (frv[x] < bv) { bv = frv[x]; bp = frp[x]; }
            selv[k] = bv; sel2[k] = bp;
            sd[bp] = INF;
        }
        __syncthreads();
    }

    if (tid < NK) {
        float dv = selv[tid];
        float wgt = (dv < INF) ? 1.0f / (dv + 1e-3f) : 0.0f;
        ws[tid] = wgt;
        wv[tid] = wgt * tvals[cand[sel2[tid]]];
    }
    __syncthreads();
    if (tid == 0) {
        float sw = 0.f, sv = 0.f;
#pragma unroll
        for (int k = 0; k < NK; k++) { sw += ws[k]; sv += wv[k]; }
        out[q] = sv / sw;
    }
}

// ---------------------------------------------------------------------------
extern "C" void kernel_launch(void* const* d_in, const int* in_sizes, int n_in,
                              void* d_out, int out_size) {
    const float* keys  = (const float*)d_in[0];   // [1024, 64]
    const float* tkeys = (const float*)d_in[1];   // [500000, 64]
    const float* tvals = (const float*)d_in[2];   // [500000]
    float* out = (float*)d_out;                   // [1024]

    prep_t<<<NPAD / 256, 256>>>(tkeys);           // 1998 blocks, exact cover
    prep_q<<<4, 256>>>(keys);
    tau_kernel<<<NB, 256>>>();                    // thresholds + counter reset
    sweep_kernel<<<NR, 512>>>();
    merge_kernel<<<NB, 256>>>(keys, tkeys, tvals, out);
}

// round 13
// speedup vs baseline: 3.4070x; 1.1061x over previous
#include <cuda_runtime.h>
#include <cstdint>

#define NB 1024
#define NC 500000
#define ND 64
#define NK 50
#define NR 148                 // sweep CTAs = one per SM
#define RC 3456                // columns per range = 27 tiles x 128
#define TPT 27
#define NPAD (NR * RC)         // 511488 padded rows
#define CAP 6144               // per-query candidate capacity
#define QS 25.0f
#define NSMP 4096              // tau sample size
#define SSTRIDE 122            // 4095*122 = 499590 < NC
#define NTAU 8                 // tau = 8th smallest sample score (~976 qualifiers)

typedef unsigned int u32;

// ------------------------- device-global scratch ---------------------------
__device__ __align__(16) unsigned char g_t8[(size_t)NPAD * 64];  // packed int8 table
__device__ int g_nint[NPAD];                                     // int norms (pad huge)
__device__ __align__(16) unsigned char g_q8[NB * 64];            // packed int8 queries
__device__ int g_tau[NB];                                        // per-query threshold
__device__ u32 g_cnt[NB];                                        // per-query counts
__device__ int g_cand[(size_t)NB * CAP];                         // candidate rows

// ------------------------------ helpers ------------------------------------
__device__ __forceinline__ u32 smem_u32(const void* p) {
    u32 a;
    asm("{ .reg .u64 t; cvta.to.shared.u64 t, %1; cvt.u32.u64 %0, t; }" : "=r"(a) : "l"(p));
    return a;
}
__device__ __forceinline__ void cpa16(u32 s, const void* g) {
    asm volatile("cp.async.cg.shared.global [%0], [%1], 16;" :: "r"(s), "l"(g));
}
__device__ __forceinline__ void cpa_commit() { asm volatile("cp.async.commit_group;" ::: "memory"); }
__device__ __forceinline__ void cpa_wait2()  { asm volatile("cp.async.wait_group 2;" ::: "memory"); }

__device__ __forceinline__ void quant_row(const float* v, u32* w, int& nint) {
    nint = 0;
#pragma unroll
    for (int j = 0; j < 16; j++) {
        u32 pk = 0;
#pragma unroll
        for (int e = 0; e < 4; e++) {
            int r = __float2int_rn(v[j * 4 + e] * QS);
            r = max(-127, min(127, r));
            nint += r * r;
            pk |= ((u32)(r & 255)) << (8 * e);
        }
        w[j] = pk;
    }
}
__device__ __forceinline__ void load16(const unsigned char* src, u32* w) {
    const uint4* p = (const uint4*)src;
#pragma unroll
    for (int i = 0; i < 4; i++) {
        uint4 x = p[i];
        w[4 * i] = x.x; w[4 * i + 1] = x.y; w[4 * i + 2] = x.z; w[4 * i + 3] = x.w;
    }
}

// ---------------------------------------------------------------------------
// prep_t: fp32 table -> packed int8 rows + int norms (padded rows never qualify)
// ---------------------------------------------------------------------------
__global__ void __launch_bounds__(256)
prep_t(const float* __restrict__ tkeys) {
    const int p = blockIdx.x * 256 + threadIdx.x;   // grid covers NPAD exactly
    u32 w[16];
    int nint;
    if (p < NC) {
        float v[ND];
        const float4* sp = (const float4*)(tkeys + (size_t)p * ND);
#pragma unroll
        for (int i = 0; i < 16; i++) {
            float4 x = __ldg(sp + i);
            v[4 * i] = x.x; v[4 * i + 1] = x.y; v[4 * i + 2] = x.z; v[4 * i + 3] = x.w;
        }
        quant_row(v, w, nint);
    } else {
#pragma unroll
        for (int i = 0; i < 16; i++) w[i] = 0;
        nint = 1 << 29;                              // never below any tau
    }
    uint4* dst = (uint4*)(g_t8 + (size_t)p * 64);
    dst[0] = make_uint4(w[0], w[1], w[2], w[3]);
    dst[1] = make_uint4(w[4], w[5], w[6], w[7]);
    dst[2] = make_uint4(w[8], w[9], w[10], w[11]);
    dst[3] = make_uint4(w[12], w[13], w[14], w[15]);
    g_nint[p] = nint;
}

// prep_q: quantize queries
__global__ void __launch_bounds__(256)
prep_q(const float* __restrict__ keys) {
    const int p = blockIdx.x * 256 + threadIdx.x;
    if (p >= NB) return;
    float v[ND];
    const float4* sp = (const float4*)(keys + (size_t)p * ND);
#pragma unroll
    for (int i = 0; i < 16; i++) {
        float4 x = __ldg(sp + i);
        v[4 * i] = x.x; v[4 * i + 1] = x.y; v[4 * i + 2] = x.z; v[4 * i + 3] = x.w;
    }
    u32 w[16]; int nint;
    quant_row(v, w, nint);
    uint4* dst = (uint4*)(g_q8 + (size_t)p * 64);
    dst[0] = make_uint4(w[0], w[1], w[2], w[3]);
    dst[1] = make_uint4(w[4], w[5], w[6], w[7]);
    dst[2] = make_uint4(w[8], w[9], w[10], w[11]);
    dst[3] = make_uint4(w[12], w[13], w[14], w[15]);
}

// ---------------------------------------------------------------------------
// tau_kernel: per-query threshold from 4096-row sample; also resets counter
// ---------------------------------------------------------------------------
__global__ void __launch_bounds__(256)
tau_kernel() {
    __shared__ int s_s[NSMP];                 // 16KB sample scores
    __shared__ int rv[8], rp[8];
    __shared__ int s_tau;

    const int q = blockIdx.x, tid = threadIdx.x;
    const int w = tid >> 5, lane = tid & 31;

    u32 qw[16];
    load16(g_q8 + (size_t)q * 64, qw);

#pragma unroll
    for (int i = 0; i < NSMP / 256; i++) {
        const int j = tid + i * 256;
        const int r = j * SSTRIDE;
        u32 tw[16];
        load16(g_t8 + (size_t)r * 64, tw);
        int d = 0;
#pragma unroll
        for (int k = 0; k < 16; k++) d = __dp4a((int)tw[k], (int)qw[k], d);
        s_s[j] = g_nint[r] - 2 * d;
    }
    __syncthreads();

    for (int k = 0; k < NTAU; k++) {
        int v = 0x7FFFFFFF, p = 0;
        for (int i = tid; i < NSMP; i += 256)
            if (s_s[i] < v) { v = s_s[i]; p = i; }
#pragma unroll
        for (int o = 16; o > 0; o >>= 1) {
            int ov = __shfl_down_sync(0xffffffffu, v, o);
            int op = __shfl_down_sync(0xffffffffu, p, o);
            if (ov < v) { v = ov; p = op; }
        }
        if (lane == 0) { rv[w] = v; rp[w] = p; }
        __syncthreads();
        if (tid == 0) {
            int bv = rv[0], bp = rp[0];
#pragma unroll
            for (int x = 1; x < 8; x++)
                if (rv[x] < bv) { bv = rv[x]; bp = rp[x]; }
            s_s[bp] = 0x7FFFFFFF;
            if (k == NTAU - 1) s_tau = bv;
        }
        __syncthreads();
    }
    if (tid == 0) { g_tau[q] = s_tau; g_cnt[q] = 0u; }
}

// ---------------------------------------------------------------------------
// sweep: dp4a sweep, software-pipelined smem column loads (A/B reg buffers),
// threshold test, append qualifiers. 148 CTAs x 512 threads, 2 queries/thread
// ---------------------------------------------------------------------------
__global__ void __launch_bounds__(512)
sweep_kernel() {
    __shared__ __align__(16) u32 s_t[3][2048];   // 3 x 8KB tile
    __shared__ __align__(16) int s_n[3][128];

    const int tid = threadIdx.x;
    const int range = blockIdx.x;
    const int q0 = tid * 2, q1 = q0 + 1;
    const u32 sbt = smem_u32(&s_t[0][0]);
    const u32 sbn = smem_u32(&s_n[0][0]);

    u32 q0w[16], q1w[16];
    load16(g_q8 + (size_t)q0 * 64, q0w);
    load16(g_q8 + (size_t)q1 * 64, q1w);
    const int t0 = g_tau[q0] + 1;     // strict < t  <=>  s <= tau
    const int t1 = g_tau[q1] + 1;

    const size_t rbase = (size_t)range * RC;
    auto prefetch = [&](int t, int st) {
        const unsigned char* src = g_t8 + (rbase + (size_t)t * 128) * 64;
        cpa16(sbt + st * 8192 + tid * 16, src + tid * 16);
        if (tid < 32)
            cpa16(sbn + st * 512 + tid * 16,
                  (const unsigned char*)(g_nint + rbase + (size_t)t * 128) + tid * 16);
        cpa_commit();
    };

    prefetch(0, 0); prefetch(1, 1); prefetch(2, 2);

// load 2 columns (c, c+1) + their norms into register buffer
#define LOADC(X0, X1, X2, X3, Y0, Y1, Y2, Y3, NX, NY, C)            \
    {                                                               \
        const uint4* _ta = (const uint4*)(tp + (C) * 16);           \
        const uint4* _tb = (const uint4*)(tp + ((C) + 1) * 16);     \
        X0 = _ta[0]; X1 = _ta[1]; X2 = _ta[2]; X3 = _ta[3];         \
        Y0 = _tb[0]; Y1 = _tb[1]; Y2 = _tb[2]; Y3 = _tb[3];         \
        NX = np[(C)]; NY = np[(C) + 1];                             \
    }

// score 2 columns vs 2 queries; append qualifiers
#define COMPUTE(X0, X1, X2, X3, Y0, Y1, Y2, Y3, NX, NY, C)          \
    {                                                               \
        int da0 = 0, db0 = 0, da1 = 0, db1 = 0;                     \
        da0 = __dp4a((int)X0.x, (int)q0w[0], da0);                  \
        db0 = __dp4a((int)Y0.x, (int)q0w[0], db0);                  \
        da1 = __dp4a((int)X0.x, (int)q1w[0], da1);                  \
        db1 = __dp4a((int)Y0.x, (int)q1w[0], db1);                  \
        da0 = __dp4a((int)X0.y, (int)q0w[1], da0);                  \
        db0 = __dp4a((int)Y0.y, (int)q0w[1], db0);                  \
        da1 = __dp4a((int)X0.y, (int)q1w[1], da1);                  \
        db1 = __dp4a((int)Y0.y, (int)q1w[1], db1);                  \
        da0 = __dp4a((int)X0.z, (int)q0w[2], da0);                  \
        db0 = __dp4a((int)Y0.z, (int)q0w[2], db0);                  \
        da1 = __dp4a((int)X0.z, (int)q1w[2], da1);                  \
        db1 = __dp4a((int)Y0.z, (int)q1w[2], db1);                  \
        da0 = __dp4a((int)X0.w, (int)q0w[3], da0);                  \
        db0 = __dp4a((int)Y0.w, (int)q0w[3], db0);                  \
        da1 = __dp4a((int)X0.w, (int)q1w[3], da1);                  \
        db1 = __dp4a((int)Y0.w, (int)q1w[3], db1);                  \
        da0 = __dp4a((int)X1.x, (int)q0w[4], da0);                  \
        db0 = __dp4a((int)Y1.x, (int)q0w[4], db0);                  \
        da1 = __dp4a((int)X1.x, (int)q1w[4], da1);                  \
        db1 = __dp4a((int)Y1.x, (int)q1w[4], db1);                  \
        da0 = __dp4a((int)X1.y, (int)q0w[5], da0);                  \
        db0 = __dp4a((int)Y1.y, (int)q0w[5], db0);                  \
        da1 = __dp4a((int)X1.y, (int)q1w[5], da1);                  \
        db1 = __dp4a((int)Y1.y, (int)q1w[5], db1);                  \
        da0 = __dp4a((int)X1.z, (int)q0w[6], da0);                  \
        db0 = __dp4a((int)Y1.z, (int)q0w[6], db0);                  \
        da1 = __dp4a((int)X1.z, (int)q1w[6], da1);                  \
        db1 = __dp4a((int)Y1.z, (int)q1w[6], db1);                  \
        da0 = __dp4a((int)X1.w, (int)q0w[7], da0);                  \
        db0 = __dp4a((int)Y1.w, (int)q0w[7], db0);                  \
        da1 = __dp4a((int)X1.w, (int)q1w[7], da1);                  \
        db1 = __dp4a((int)Y1.w, (int)q1w[7], db1);                  \
        da0 = __dp4a((int)X2.x, (int)q0w[8], da0);                  \
        db0 = __dp4a((int)Y2.x, (int)q0w[8], db0);                  \
        da1 = __dp4a((int)X2.x, (int)q1w[8], da1);                  \
        db1 = __dp4a((int)Y2.x, (int)q1w[8], db1);                  \
        da0 = __dp4a((int)X2.y, (int)q0w[9], da0);                  \
        db0 = __dp4a((int)Y2.y, (int)q0w[9], db0);                  \
        da1 = __dp4a((int)X2.y, (int)q1w[9], da1);                  \
        db1 = __dp4a((int)Y2.y, (int)q1w[9], db1);                  \
        da0 = __dp4a((int)X2.z, (int)q0w[10], da0);                 \
        db0 = __dp4a((int)Y2.z, (int)q0w[10], db0);                 \
        da1 = __dp4a((int)X2.z, (int)q1w[10], da1);                 \
        db1 = __dp4a((int)Y2.z, (int)q1w[10], db1);                 \
        da0 = __dp4a((int)X2.w, (int)q0w[11], da0);                 \
        db0 = __dp4a((int)Y2.w, (int)q0w[11], db0);                 \
        da1 = __dp4a((int)X2.w, (int)q1w[11], da1);                 \
        db1 = __dp4a((int)Y2.w, (int)q1w[11], db1);                 \
        da0 = __dp4a((int)X3.x, (int)q0w[12], da0);                 \
        db0 = __dp4a((int)Y3.x, (int)q0w[12], db0);                 \
        da1 = __dp4a((int)X3.x, (int)q1w[12], da1);                 \
        db1 = __dp4a((int)Y3.x, (int)q1w[12], db1);                 \
        da0 = __dp4a((int)X3.y, (int)q0w[13], da0);                 \
        db0 = __dp4a((int)Y3.y, (int)q0w[13], db0);                 \
        da1 = __dp4a((int)X3.y, (int)q1w[13], da1);                 \
        db1 = __dp4a((int)Y3.y, (int)q1w[13], db1);                 \
        da0 = __dp4a((int)X3.z, (int)q0w[14], da0);                 \
        db0 = __dp4a((int)Y3.z, (int)q0w[14], db0);                 \
        da1 = __dp4a((int)X3.z, (int)q1w[14], da1);                 \
        db1 = __dp4a((int)Y3.z, (int)q1w[14], db1);                 \
        da0 = __dp4a((int)X3.w, (int)q0w[15], da0);                 \
        db0 = __dp4a((int)Y3.w, (int)q0w[15], db0);                 \
        da1 = __dp4a((int)X3.w, (int)q1w[15], da1);                 \
        db1 = __dp4a((int)Y3.w, (int)q1w[15], db1);                 \
        const int sa0 = NX - 2 * da0, sb0 = NY - 2 * db0;           \
        const int sa1 = NX - 2 * da1, sb1 = NY - 2 * db1;           \
        const int m = min(min(sa0, sb0) - t0, min(sa1, sb1) - t1);  \
        if (m < 0) {                                                \
            const int p0 = pbase + (C);                             \
            if (sa0 < t0) {                                         \
                u32 i = atomicAdd(&g_cnt[q0], 1u);                  \
                if (i < CAP) g_cand[(size_t)q0 * CAP + i] = p0;     \
            }                                                       \
            if (sb0 < t0) {                                         \
                u32 i = atomicAdd(&g_cnt[q0], 1u);                  \
                if (i < CAP) g_cand[(size_t)q0 * CAP + i] = p0 + 1; \
            }                                                       \
            if (sa1 < t1) {                                         \
                u32 i = atomicAdd(&g_cnt[q1], 1u);                  \
                if (i < CAP) g_cand[(size_t)q1 * CAP + i] = p0;     \
            }                                                       \
            if (sb1 < t1) {                                         \
                u32 i = atomicAdd(&g_cnt[q1], 1u);                  \
                if (i < CAP) g_cand[(size_t)q1 * CAP + i] = p0 + 1; \
            }                                                       \
        }                                                           \
    }

    for (int t = 0; t < TPT; t++) {
        const int st = t % 3;
        cpa_wait2();
        __syncthreads();

        const u32* tp = s_t[st];
        const int* np = s_n[st];
        const int pbase = range * RC + t * 128;

        uint4 A0, A1, A2, A3, A4, A5, A6, A7;
        uint4 B0, B1, B2, B3, B4, B5, B6, B7;
        int nA0, nA1, nB0, nB1;

        LOADC(A0, A1, A2, A3, A4, A5, A6, A7, nA0, nA1, 0);
#pragma unroll 4
        for (int c = 0; c < 128; c += 4) {
            LOADC(B0, B1, B2, B3, B4, B5, B6, B7, nB0, nB1, c + 2);
            COMPUTE(A0, A1, A2, A3, A4, A5, A6, A7, nA0, nA1, c);
            LOADC(A0, A1, A2, A3, A4, A5, A6, A7, nA0, nA1, (c + 4) & 127);
            COMPUTE(B0, B1, B2, B3, B4, B5, B6, B7, nB0, nB1, c + 2);
        }

        __syncthreads();
        if (t + 3 < TPT) prefetch(t + 3, st);
        else cpa_commit();
    }
#undef LOADC
#undef COMPUTE
}

// ---------------------------------------------------------------------------
// merge: exact fp32 rerank of qualifiers -> exact top-50 -> weighted average
// ---------------------------------------------------------------------------
__global__ void __launch_bounds__(256)
merge_kernel(const float* __restrict__ keys, const float* __restrict__ tkeys,
             const float* __restrict__ tvals, float* __restrict__ out) {
    __shared__ float sd[CAP];                 // 24KB exact distances
    __shared__ __align__(16) float qs[ND];
    __shared__ float frv[8]; __shared__ int frp[8];
    __shared__ float selv[NK]; __shared__ int sel2[NK];
    __shared__ float ws[NK], wv[NK];

    const int q = blockIdx.x, tid = threadIdx.x;
    const int w = tid >> 5, lane = tid & 31;
    const float INF = __int_as_float(0x7f800000);
    const int n = min((int)g_cnt[q], CAP);
    const int* cand = g_cand + (size_t)q * CAP;

    if (tid < ND) qs[tid] = keys[(size_t)q * ND + tid];
    __syncthreads();

    // exact squared distances: warp per candidate (broadcast row index)
    {
        const float2 qv = ((const float2*)qs)[lane];
        for (int cb = w; cb < n; cb += 8) {
            const int row = cand[cb];
            const float2 tv = ((const float2*)(tkeys + (size_t)row * ND))[lane];
            float d0 = qv.x - tv.x, d1 = qv.y - tv.y;
            float ss = fmaf(d0, d0, d1 * d1);
#pragma unroll
            for (int o = 16; o > 0; o >>= 1) ss += __shfl_xor_sync(0xffffffffu, ss, o);
            if (lane == 0) sd[cb] = ss;
        }
    }
    __syncthreads();

    // exact top-50 by iterative argmin over n candidates
    for (int k = 0; k < NK; k++) {
        float v = INF; int p = 0;
        for (int i = tid; i < n; i += 256)
            if (sd[i] < v) { v = sd[i]; p = i; }
#pragma unroll
        for (int o = 16; o > 0; o >>= 1) {
            float ov = __shfl_down_sync(0xffffffffu, v, o);
            int   op = __shfl_down_sync(0xffffffffu, p, o);
            if (ov < v) { v = ov; p = op; }
        }
        if (lane == 0) { frv[w] = v; frp[w] = p; }
        __syncthreads();
        if (tid == 0) {
            float bv = frv[0]; int bp = frp[0];
#pragma unroll
            for (int x = 1; x < 8; x++)
                if (frv[x] < bv) { bv = frv[x]; bp = frp[x]; }
            selv[k] = bv; sel2[k] = bp;
            sd[bp] = INF;
        }
        __syncthreads();
    }

    if (tid < NK) {
        float dv = selv[tid];
        float wgt = (dv < INF) ? 1.0f / (dv + 1e-3f) : 0.0f;
        ws[tid] = wgt;
        wv[tid] = wgt * tvals[cand[sel2[tid]]];
    }
    __syncthreads();
    if (tid == 0) {
        float sw = 0.f, sv = 0.f;
#pragma unroll
        for (int k = 0; k < NK; k++) { sw += ws[k]; sv += wv[k]; }
        out[q] = sv / sw;
    }
}

// ---------------------------------------------------------------------------
extern "C" void kernel_launch(void* const* d_in, const int* in_sizes, int n_in,
                              void* d_out, int out_size) {
    const float* keys  = (const float*)d_in[0];   // [1024, 64]
    const float* tkeys = (const float*)d_in[1];   // [500000, 64]
    const float* tvals = (const float*)d_in[2];   // [500000]
    float* out = (float*)d_out;                   // [1024]

    prep_t<<<NPAD / 256, 256>>>(tkeys);           // 1998 blocks, exact cover
    prep_q<<<4, 256>>>(keys);
    tau_kernel<<<NB, 256>>>();                    // thresholds + counter reset
    sweep_kernel<<<NR, 512>>>();
    merge_kernel<<<NB, 256>>>(keys, tkeys, tvals, out);
}